// round 16
// baseline (speedup 1.0000x reference)
#include <cuda.h>
#include <cuda_runtime.h>
#include <cuda_bf16.h>
#include <cstdint>
#include <math.h>

// ============================================================================
// Problem constants
// ============================================================================
static constexpr int Bsz  = 4;
static constexpr int NH   = 8;
static constexpr int L    = 1025;
static constexpr int HD   = 512;
static constexpr int IND  = 512;
static constexpr int QKVD = 4096;
static constexpr int BH   = Bsz * NH;          // 32
static constexpr int MQ   = Bsz * L;           // 4100
static constexpr int MP   = 4224;              // padded M rows (33*128)
static constexpr int LR   = 1152;              // padded rows per (b,n) (9*128)
static constexpr int KA   = 1088;              // padded attn K cols (17*64)
static constexpr int LP   = 1028;              // fp32 logits row stride

// ============================================================================
// Global scratch (zero-initialized; pad regions never written)
// ============================================================================
__device__ __align__(16) __nv_bfloat16 g_xh[MP * IND];
__device__ __align__(16) __nv_bfloat16 g_xl[MP * IND];
__device__ __align__(16) __nv_bfloat16 g_Wh[3][QKVD * IND];
__device__ __align__(16) __nv_bfloat16 g_Wl[3][QKVD * IND];
__device__ __align__(16) __nv_bfloat16 g_Wph[3][HD * HD];
__device__ __align__(16) __nv_bfloat16 g_Wpl[3][HD * HD];
__device__ __align__(16) __nv_bfloat16 g_Wdh[IND * QKVD];
__device__ __align__(16) __nv_bfloat16 g_Wdl[IND * QKVD];
__device__ __align__(16) __nv_bfloat16 g_QKVh[3][(size_t)BH * L * HD];
__device__ __align__(16) __nv_bfloat16 g_QKVl[3][(size_t)BH * L * HD];
__device__ __align__(16) __nv_bfloat16 g_Ph[2][(size_t)BH * LR * HD];    // PQ, PK (token-major)
__device__ __align__(16) __nv_bfloat16 g_Pl[2][(size_t)BH * LR * HD];
__device__ __align__(16) __nv_bfloat16 g_PVh[(size_t)BH * LR * HD];      // PV token-major
__device__ __align__(16) __nv_bfloat16 g_PVl[(size_t)BH * LR * HD];
__device__ __align__(16) __nv_bfloat16 g_PVth[(size_t)BH * HD * LR];     // PV transposed [hd][token]
__device__ __align__(16) __nv_bfloat16 g_PVtl[(size_t)BH * HD * LR];
__device__ __align__(16) float         g_logits[(size_t)BH * L * LP];
__device__ __align__(16) __nv_bfloat16 g_ah[(size_t)BH * LR * KA];
__device__ __align__(16) __nv_bfloat16 g_al[(size_t)BH * LR * KA];
__device__ __align__(16) __nv_bfloat16 g_sh[(size_t)MP * QKVD];
__device__ __align__(16) __nv_bfloat16 g_sl[(size_t)MP * QKVD];
__device__ __align__(16) float         g_emb[1024 * HD];                 // 2D pos-embed table

// ============================================================================
// GEMM core v5: 128x128 CTA tile, 8 warps of 64x32, KC=32 k-chunks.
// TMA 2D loads into SW64-swizzled 128x64B tiles, 3-stage mbarrier pipeline.
// ============================================================================
#define KC 32
static constexpr uint32_t TILE_B = 128 * KC * 2;      // 8192 bytes per tile
static constexpr uint32_t STG_B  = 4 * TILE_B;        // 32768 per stage
static constexpr uint32_t NSTG   = 3;
static constexpr uint32_t MB_OFF = NSTG * STG_B;      // 98304
static constexpr size_t   SMEM_BYTES = NSTG * STG_B + 64 + 1024;  // + barriers + align slack

__device__ __forceinline__ uint32_t smem_u32(const void* p) {
    uint32_t a;
    asm("{ .reg .u64 t; cvta.to.shared.u64 t, %1; cvt.u32.u64 %0, t; }" : "=r"(a) : "l"(p));
    return a;
}

__device__ __forceinline__ void mma_bf16(float* d,
    const uint32_t* a, uint32_t b0, uint32_t b1)
{
    asm volatile(
        "mma.sync.aligned.m16n8k16.row.col.f32.bf16.bf16.f32 "
        "{%0,%1,%2,%3}, {%4,%5,%6,%7}, {%8,%9}, {%0,%1,%2,%3};"
        : "+f"(d[0]), "+f"(d[1]), "+f"(d[2]), "+f"(d[3])
        : "r"(a[0]), "r"(a[1]), "r"(a[2]), "r"(a[3]), "r"(b0), "r"(b1));
}

__device__ __forceinline__ void ldsm4(uint32_t* r, uint32_t addr) {
    asm volatile("ldmatrix.sync.aligned.m8n8.x4.shared.b16 {%0,%1,%2,%3}, [%4];"
        : "=r"(r[0]), "=r"(r[1]), "=r"(r[2]), "=r"(r[3]) : "r"(addr));
}

#define MBARRIER_INIT(mb, cnt) \
    asm volatile("mbarrier.init.shared.b64 [%0], %1;" :: "r"((uint32_t)(mb)), "r"((uint32_t)(cnt)) : "memory")
#define MBARRIER_EXPECT_TX(mb, tx) \
    asm volatile("mbarrier.arrive.expect_tx.shared.b64 _, [%0], %1;" :: "r"((uint32_t)(mb)), "r"((uint32_t)(tx)) : "memory")

#define MBARRIER_WAIT_PARITY(mbar_smem_addr, phase_parity) do { \
    uint32_t _mbar = (uint32_t)(mbar_smem_addr); \
    uint32_t _parity = (uint32_t)(phase_parity); \
    uint32_t _done; \
    asm volatile( \
        "{\n\t.reg .pred p;\n\t" \
        "mbarrier.try_wait.parity.acquire.cta.shared::cta.b64 p, [%1], %2;\n\t" \
        "selp.b32 %0, 1, 0, p;\n\t}" \
        : "=r"(_done) : "r"(_mbar), "r"(_parity) : "memory"); \
    if (!_done) { \
        asm volatile( \
            "{\n\t.reg .pred P1;\n\t" \
            "WAIT_LOOP_%=:\n\t" \
            "mbarrier.try_wait.parity.acquire.cta.shared::cta.b64 P1, [%0], %1, 0x989680;\n\t" \
            "@P1 bra.uni WAIT_DONE_%=;\n\t" \
            "bra.uni WAIT_LOOP_%=;\n\t" \
            "WAIT_DONE_%=:\n\t}" \
            :: "r"(_mbar), "r"(_parity) : "memory"); \
    } \
} while(0)

#define TMA_LOAD_2D(dst, map, cx, cy, mb) \
    asm volatile("cp.async.bulk.tensor.2d.shared::cta.global.tile.mbarrier::complete_tx::bytes " \
        "[%0], [%1, {%2, %3}], [%4];" \
        :: "r"((uint32_t)(dst)), "l"(map), "r"((int)(cx)), "r"((int)(cy)), "r"((uint32_t)(mb)) : "memory")

// SW64 swizzle on logical byte offset within a 128x64B tile
__device__ __forceinline__ uint32_t sw64(uint32_t off) { return off ^ ((off >> 3) & 0x30); }

__device__ __forceinline__ void tma_issue(uint32_t stg0, uint32_t mb0, int u,
    const CUtensorMap* mAh, const CUtensorMap* mAl,
    const CUtensorMap* mBh, const CUtensorMap* mBl, int yA, int yB)
{
    uint32_t su = (uint32_t)(u % NSTG);
    uint32_t dst = stg0 + su * STG_B;
    uint32_t mb  = mb0 + su * 8;
    int cx = u * KC;
    MBARRIER_EXPECT_TX(mb, STG_B);
    TMA_LOAD_2D(dst + 0 * TILE_B, mAh, cx, yA, mb);
    TMA_LOAD_2D(dst + 1 * TILE_B, mAl, cx, yA, mb);
    TMA_LOAD_2D(dst + 2 * TILE_B, mBh, cx, yB, mb);
    TMA_LOAD_2D(dst + 3 * TILE_B, mBl, cx, yB, mb);
}

__device__ __forceinline__ void gemm_tma(uint32_t sbase,
    const CUtensorMap* mAh, const CUtensorMap* mAl,
    const CUtensorMap* mBh, const CUtensorMap* mBl,
    int yA, int yB, int kt, float acc[4][4][4])
{
    const int tid = threadIdx.x, lane = tid & 31, wid = tid >> 5;
    const int wm = wid >> 2, wn = wid & 3;
    const int lrow = (lane & 7) + ((lane >> 3) & 1) * 8;
    const int lcolb = (lane >> 4) * 16;      // byte offset within row

    const uint32_t stg0 = sbase, mb0 = sbase + MB_OFF;

    if (tid == 0) {
        for (uint32_t s = 0; s < NSTG; s++) MBARRIER_INIT(mb0 + s * 8, 1);
    }
    __syncthreads();
    if (tid == 0) {
        tma_issue(stg0, mb0, 0, mAh, mAl, mBh, mBl, yA, yB);
        if (kt > 1) tma_issue(stg0, mb0, 1, mAh, mAl, mBh, mBl, yA, yB);
    }

    int ph0 = 0, ph1 = 0, ph2 = 0;
    for (int t = 0; t < kt; t++) {
        const int s = t % NSTG;
        if (s == 0)      { MBARRIER_WAIT_PARITY(mb0 + 0, ph0); ph0 ^= 1; }
        else if (s == 1) { MBARRIER_WAIT_PARITY(mb0 + 8, ph1); ph1 ^= 1; }
        else             { MBARRIER_WAIT_PARITY(mb0 + 16, ph2); ph2 ^= 1; }

        const uint32_t so = stg0 + (uint32_t)s * STG_B;
        const uint32_t tAh = so, tAl = so + TILE_B, tBh = so + 2 * TILE_B, tBl = so + 3 * TILE_B;
#pragma unroll
        for (int kk = 0; kk < 2; kk++) {
            const int kb = kk * 32 + lcolb;          // byte offset in 64B row
            uint32_t bh[2][4], bl[2][4];
#pragma unroll
            for (int jj = 0; jj < 2; jj++) {
                uint32_t off = sw64((uint32_t)((wn * 32 + jj * 16 + lrow) * 64 + kb));
                ldsm4(bh[jj], tBh + off);
                ldsm4(bl[jj], tBl + off);
            }
#pragma unroll
            for (int i = 0; i < 4; i++) {
                uint32_t ah[4], al[4];
                uint32_t off = sw64((uint32_t)((wm * 64 + i * 16 + lrow) * 64 + kb));
                ldsm4(ah, tAh + off);
                ldsm4(al, tAl + off);
#pragma unroll
                for (int j = 0; j < 4; j++) {
                    uint32_t b0 = bh[j >> 1][j & 1], b1 = bh[j >> 1][2 + (j & 1)];
                    uint32_t c0 = bl[j >> 1][j & 1], c1 = bl[j >> 1][2 + (j & 1)];
                    mma_bf16(acc[i][j], ah, b0, b1);
                    mma_bf16(acc[i][j], ah, c0, c1);
                    mma_bf16(acc[i][j], al, b0, b1);
                }
            }
        }
        __syncthreads();                              // all warps done with stage s
        if (tid == 0 && t + 2 < kt)
            tma_issue(stg0, mb0, t + 2, mAh, mAl, mBh, mBl, yA, yB);
    }
}

__device__ __forceinline__ void split_bf(float v, __nv_bfloat16* hp, __nv_bfloat16* lp) {
    __nv_bfloat16 h = __float2bfloat16(v);
    *hp = h;
    *lp = __float2bfloat16(v - __bfloat162float(h));
}

#define EPI_SETUP() \
    const int lane = threadIdx.x & 31, wid_ = threadIdx.x >> 5; \
    const int wm = wid_ >> 2, wn = wid_ & 3; \
    const int er0 = wm * 64 + (lane >> 2); \
    const int ec0 = wn * 32 + (lane & 3) * 2;

#define SMEM_PROLOG() \
    extern __shared__ char smem_raw[]; \
    uint32_t sbase = (smem_u32(smem_raw) + 1023u) & ~1023u;

// ============================================================================
// Pos-embed table
// ============================================================================
__global__ __launch_bounds__(256) void k_pos()
{
    int idx = blockIdx.x * 256 + threadIdx.x;
    if (idx >= 1024 * HD) return;
    int s = idx >> 9, o = idx & 511;
    const float LOG1E4_128 = 9.210340371976184f / 128.0f;
    int yg = s >> 5, xg = s & 31;
    float omega = expf(-(float)(o & 127) * LOG1E4_128);
    float e;
    if (o < 128)      e = sinf((float)yg * omega);
    else if (o < 256) e = cosf((float)yg * omega);
    else if (o < 384) e = sinf((float)xg * omega);
    else              e = cosf((float)xg * omega);
    g_emb[idx] = e;
}

// ============================================================================
// Fused conversion: fp32 -> bf16 hi/lo, 8 segments
// ============================================================================
struct ConvSeg { const float* s; __nv_bfloat16* h; __nv_bfloat16* l; int n4; };
struct ConvArgs { ConvSeg seg[8]; };

__global__ __launch_bounds__(256) void k_conv_all(ConvArgs a)
{
    ConvSeg sg = a.seg[blockIdx.y];
    int i = blockIdx.x * 256 + threadIdx.x;
    if (i >= sg.n4) return;
    float4 v = ((const float4*)sg.s)[i];
    __nv_bfloat16 h0, h1, h2, h3, l0, l1, l2, l3;
    split_bf(v.x, &h0, &l0); split_bf(v.y, &h1, &l1);
    split_bf(v.z, &h2, &l2); split_bf(v.w, &h3, &l3);
    ushort4 hv = make_ushort4(*(unsigned short*)&h0, *(unsigned short*)&h1,
                              *(unsigned short*)&h2, *(unsigned short*)&h3);
    ushort4 lv = make_ushort4(*(unsigned short*)&l0, *(unsigned short*)&l1,
                              *(unsigned short*)&l2, *(unsigned short*)&l3);
    *(ushort4*)(sg.h + (size_t)i * 4) = hv;
    *(ushort4*)(sg.l + (size_t)i * 4) = lv;
}

// ============================================================================
// QKV projection.  grid (32, 33, 3)
// ============================================================================
__global__ __launch_bounds__(256, 2) void k_qkv_mma(
    const float* __restrict__ bq, const float* __restrict__ bk, const float* __restrict__ bv,
    const __grid_constant__ CUtensorMap mAh, const __grid_constant__ CUtensorMap mAl,
    const __grid_constant__ CUtensorMap mBh, const __grid_constant__ CUtensorMap mBl)
{
    SMEM_PROLOG();
    const int z = blockIdx.z;
    const int row0 = blockIdx.y * 128, col0 = blockIdx.x * 128;
    const float* bias = (z == 0) ? bq : (z == 1) ? bk : bv;

    float acc[4][4][4] = {};
    gemm_tma(sbase, &mAh, &mAl, &mBh, &mBl, row0, z * QKVD + col0, IND / KC, acc);

    EPI_SETUP();
    __nv_bfloat16* oh = g_QKVh[z];
    __nv_bfloat16* ol = g_QKVl[z];
#pragma unroll
    for (int i = 0; i < 4; i++)
#pragma unroll
        for (int p2 = 0; p2 < 2; p2++) {
            int m = row0 + er0 + i * 16 + p2 * 8;
            if (m >= MQ) continue;
            int bb = m / L, l = m - bb * L;
#pragma unroll
            for (int j = 0; j < 4; j++)
#pragma unroll
                for (int p1 = 0; p1 < 2; p1++) {
                    int o = col0 + ec0 + j * 8 + p1;
                    int n = o >> 9, ch = o & 511;
                    float v = acc[i][j][p2 * 2 + p1] + bias[o];
                    size_t idx = (((size_t)(bb * NH + n)) * L + l) * HD + ch;
                    split_bf(v, &oh[idx], &ol[idx]);
                }
        }
}

// ============================================================================
// cls passthrough (token 0 into token-major pooled buffers)
// ============================================================================
__global__ __launch_bounds__(256) void k_cls2()
{
    int idx = blockIdx.x * 256 + threadIdx.x;
    if (idx >= 3 * BH * HD) return;
    int z = idx / (BH * HD), rem = idx % (BH * HD);
    int bn = rem / HD, c = rem % HD;
    size_t so = ((size_t)bn * L) * HD + c;
    size_t d  = ((size_t)bn * LR) * HD + c;
    if (z < 2) {
        g_Ph[z][d] = g_QKVh[z][so];
        g_Pl[z][d] = g_QKVl[z][so];
    } else {
        g_PVh[d] = g_QKVh[2][so];
        g_PVl[d] = g_QKVl[2][so];
    }
}

// ============================================================================
// Pooler GEMM.  grid (4, 256, 3).  ALL outputs token-major (coalesced);
// PV transpose moved to dedicated k_pvt kernel.
// ============================================================================
__global__ __launch_bounds__(256, 2) void k_pool_mma(
    const float* __restrict__ bpq, const float* __restrict__ bpk, const float* __restrict__ bpv,
    const __grid_constant__ CUtensorMap mAh, const __grid_constant__ CUtensorMap mAl,
    const __grid_constant__ CUtensorMap mBh, const __grid_constant__ CUtensorMap mBl)
{
    SMEM_PROLOG();
    const int z = blockIdx.z;
    const int bn = blockIdx.y >> 3, mt = blockIdx.y & 7;
    const int col0 = blockIdx.x * 128;
    const float* bias = (z == 0) ? bpq : (z == 1) ? bpk : bpv;

    int yA = z * (BH * L) + bn * L + 1 + mt * 128;
    int yB = z * HD + col0;
    float acc[4][4][4] = {};
    gemm_tma(sbase, &mAh, &mAl, &mBh, &mBl, yA, yB, HD / KC, acc);

    EPI_SETUP();
    __nv_bfloat16* dh = (z == 0) ? g_Ph[0] : (z == 1) ? g_Ph[1] : g_PVh;
    __nv_bfloat16* dl = (z == 0) ? g_Pl[0] : (z == 1) ? g_Pl[1] : g_PVl;
#pragma unroll
    for (int i = 0; i < 4; i++)
#pragma unroll
        for (int p2 = 0; p2 < 2; p2++) {
            int s = mt * 128 + er0 + i * 16 + p2 * 8;     // spatial token 0..1023
#pragma unroll
            for (int j = 0; j < 4; j++)
#pragma unroll
                for (int p1 = 0; p1 < 2; p1++) {
                    int o = col0 + ec0 + j * 8 + p1;
                    float v = acc[i][j][p2 * 2 + p1] + bias[o];
                    if (z == 0) v += g_emb[(size_t)s * HD + o];
                    size_t idx = ((size_t)bn * LR + 1 + s) * HD + o;
                    split_bf(v, &dh[idx], &dl[idx]);
                }
        }
}

// ============================================================================
// PV transpose: [token, hd] -> [hd, token], 64x64 smem tiles, coalesced both
// sides.  Tile row stride 72 elems (144 B, 16B-multiple) so uint4 ops on any
// row are aligned (R15 crash: stride 65 -> 130 B broke STS.128 alignment).
// grid (LR/64, HD/64, BH).  Covers all 1152 tokens incl. cls + pad.
// ============================================================================
__global__ __launch_bounds__(256) void k_pvt()
{
    __shared__ __align__(16) __nv_bfloat16 tile[64][72];
    const int bn = blockIdx.z;
    const int t0 = blockIdx.x * 64, h0 = blockIdx.y * 64;
    const int tid = threadIdx.x;

#pragma unroll
    for (int half = 0; half < 2; half++) {
        const __nv_bfloat16* src = half ? g_PVl : g_PVh;
        __nv_bfloat16* dst = half ? g_PVtl : g_PVth;
        if (half) __syncthreads();
        // load 64 token-rows x 64 hd-cols (row-major, uint4 = 8 bf16)
        for (int q = tid; q < 512; q += 256) {
            int r = q >> 3, c = (q & 7) * 8;
            uint4 v = *(const uint4*)(src + ((size_t)bn * LR + t0 + r) * HD + h0 + c);
            *(uint4*)&tile[r][c] = v;
        }
        __syncthreads();
        // store transposed: 64 hd-rows x 64 token-cols
        for (int q = tid; q < 512; q += 256) {
            int h = q >> 3, t = (q & 7) * 8;
            unsigned short u[8];
#pragma unroll
            for (int s = 0; s < 8; s++) u[s] = *(unsigned short*)&tile[t + s][h];
            *(uint4*)(dst + ((size_t)bn * HD + h0 + h) * LR + t0 + t) = *(uint4*)u;
        }
    }
}

// ============================================================================
// Logits = PQ * PK^T * scale.  grid (9, 9, 32)
// ============================================================================
__global__ __launch_bounds__(256, 2) void k_logits_mma(
    const __grid_constant__ CUtensorMap mAh, const __grid_constant__ CUtensorMap mAl,
    const __grid_constant__ CUtensorMap mBh, const __grid_constant__ CUtensorMap mBl)
{
    SMEM_PROLOG();
    const int bn = blockIdx.z;
    const int row0 = blockIdx.y * 128, col0 = blockIdx.x * 128;

    float acc[4][4][4] = {};
    gemm_tma(sbase, &mAh, &mAl, &mBh, &mBl, bn * LR + row0, bn * LR + col0, HD / KC, acc);

    EPI_SETUP();
    const float scale = 0.044194173824159216f;   // 1/sqrt(512)
    float* dstb = g_logits + (size_t)bn * L * LP;
#pragma unroll
    for (int i = 0; i < 4; i++)
#pragma unroll
        for (int p2 = 0; p2 < 2; p2++) {
            int q = row0 + er0 + i * 16 + p2 * 8;
            if (q >= L) continue;
            float* dst = dstb + (size_t)q * LP;
#pragma unroll
            for (int j = 0; j < 4; j++)
#pragma unroll
                for (int p1 = 0; p1 < 2; p1++) {
                    int k = col0 + ec0 + j * 8 + p1;
                    if (k < L) dst[k] = acc[i][j][p2 * 2 + p1] * scale;
                }
        }
}

// ============================================================================
// Softmax -> attn hi/lo bf16.  grid (1025, 32)
// ============================================================================
__global__ __launch_bounds__(256) void k_softmax_mma()
{
    const int bn = blockIdx.y, row = blockIdx.x;
    const float* p = g_logits + ((size_t)bn * L + row) * LP;
    __nv_bfloat16* oh = g_ah + ((size_t)bn * LR + row) * KA;
    __nv_bfloat16* ol = g_al + ((size_t)bn * LR + row) * KA;
    __shared__ float red[256];
    const int tid = threadIdx.x;

    float v[5];
#pragma unroll
    for (int i = 0; i < 4; i++) v[i] = p[tid + (i << 8)];
    v[4] = (tid == 0) ? p[1024] : -1e30f;

    float m = v[0];
#pragma unroll
    for (int i = 1; i < 5; i++) m = fmaxf(m, v[i]);
    red[tid] = m; __syncthreads();
    for (int s = 128; s > 0; s >>= 1) {
        if (tid < s) red[tid] = fmaxf(red[tid], red[tid + s]);
        __syncthreads();
    }
    m = red[0]; __syncthreads();

    float sum = 0.f;
#pragma unroll
    for (int i = 0; i < 5; i++) { v[i] = expf(v[i] - m); sum += v[i]; }
    red[tid] = sum; __syncthreads();
    for (int s = 128; s > 0; s >>= 1) {
        if (tid < s) red[tid] += red[tid + s];
        __syncthreads();
    }
    float inv = 1.f / red[0];

#pragma unroll
    for (int i = 0; i < 4; i++) {
        int k = tid + (i << 8);
        split_bf(v[i] * inv, &oh[k], &ol[k]);
    }
    if (tid == 0) split_bf(v[4] * inv, &oh[1024], &ol[1024]);
}

// ============================================================================
// AV GEMM + residual + restack.  grid (4, 9, 32)
// ============================================================================
__global__ __launch_bounds__(256, 2) void k_av_mma(
    const __grid_constant__ CUtensorMap mAh, const __grid_constant__ CUtensorMap mAl,
    const __grid_constant__ CUtensorMap mBh, const __grid_constant__ CUtensorMap mBl)
{
    SMEM_PROLOG();
    const int bn = blockIdx.z;
    const int row0 = blockIdx.y * 128, col0 = blockIdx.x * 128;

    float acc[4][4][4] = {};
    gemm_tma(sbase, &mAh, &mAl, &mBh, &mBl, bn * LR + row0, bn * HD + col0, KA / KC, acc);

    EPI_SETUP();
    const int bb = bn >> 3, n = bn & 7;
#pragma unroll
    for (int i = 0; i < 4; i++)
#pragma unroll
        for (int p2 = 0; p2 < 2; p2++) {
            int l = row0 + er0 + i * 16 + p2 * 8;
            if (l >= L) continue;
            size_t qb = ((size_t)bn * L + l) * HD;
            size_t sb = ((size_t)(bb * L + l)) * QKVD + n * HD;
#pragma unroll
            for (int j = 0; j < 4; j++)
#pragma unroll
                for (int p1 = 0; p1 < 2; p1++) {
                    int c = col0 + ec0 + j * 8 + p1;
                    float v = acc[i][j][p2 * 2 + p1];
                    if (l > 0)
                        v += __bfloat162float(g_QKVh[0][qb + c]) + __bfloat162float(g_QKVl[0][qb + c]);
                    split_bf(v, &g_sh[sb + c], &g_sl[sb + c]);
                }
        }
}

// ============================================================================
// Output projection.  grid (4, 33)
// ============================================================================
__global__ __launch_bounds__(256, 2) void k_out_mma(
    const float* __restrict__ bd, float* __restrict__ out,
    const __grid_constant__ CUtensorMap mAh, const __grid_constant__ CUtensorMap mAl,
    const __grid_constant__ CUtensorMap mBh, const __grid_constant__ CUtensorMap mBl)
{
    SMEM_PROLOG();
    const int row0 = blockIdx.y * 128, col0 = blockIdx.x * 128;

    float acc[4][4][4] = {};
    gemm_tma(sbase, &mAh, &mAl, &mBh, &mBl, row0, col0, QKVD / KC, acc);

    EPI_SETUP();
#pragma unroll
    for (int i = 0; i < 4; i++)
#pragma unroll
        for (int p2 = 0; p2 < 2; p2++) {
            int m = row0 + er0 + i * 16 + p2 * 8;
            if (m >= MQ) continue;
            float* dst = out + (size_t)m * IND;
#pragma unroll
            for (int j = 0; j < 4; j++)
#pragma unroll
                for (int p1 = 0; p1 < 2; p1++) {
                    int o = col0 + ec0 + j * 8 + p1;
                    dst[o] = acc[i][j][p2 * 2 + p1] + bd[o];
                }
        }
}

// ============================================================================
// Host: tensormap encoding via driver entry point (no -lcuda needed)
// ============================================================================
typedef CUresult (*EncodeFn)(CUtensorMap*, CUtensorMapDataType, cuuint32_t, void*,
    const cuuint64_t*, const cuuint64_t*, const cuuint32_t*, const cuuint32_t*,
    CUtensorMapInterleave, CUtensorMapSwizzle, CUtensorMapL2promotion, CUtensorMapFloatOOBfill);

static void mk2d(EncodeFn enc, CUtensorMap* m, void* base, uint64_t d0, uint64_t d1)
{
    cuuint64_t dims[2] = {d0, d1};
    cuuint64_t strides[1] = {d0 * 2};          // bf16
    cuuint32_t box[2] = {KC, 128};
    cuuint32_t es[2] = {1, 1};
    enc(m, CU_TENSOR_MAP_DATA_TYPE_UINT16, 2, base, dims, strides, box, es,
        CU_TENSOR_MAP_INTERLEAVE_NONE, CU_TENSOR_MAP_SWIZZLE_64B,
        CU_TENSOR_MAP_L2_PROMOTION_L2_128B, CU_TENSOR_MAP_FLOAT_OOB_FILL_NONE);
}

extern "C" void kernel_launch(void* const* d_in, const int* in_sizes, int n_in,
                              void* d_out, int out_size)
{
    const float* x   = (const float*)d_in[0];
    const float* Wq  = (const float*)d_in[1];
    const float* bq  = (const float*)d_in[2];
    const float* Wk  = (const float*)d_in[3];
    const float* bk  = (const float*)d_in[4];
    const float* Wv  = (const float*)d_in[5];
    const float* bv  = (const float*)d_in[6];
    const float* Wpq = (const float*)d_in[7];
    const float* bpq = (const float*)d_in[8];
    const float* Wpk = (const float*)d_in[9];
    const float* bpk = (const float*)d_in[10];
    const float* Wpv = (const float*)d_in[11];
    const float* bpv = (const float*)d_in[12];
    const float* Wd  = (const float*)d_in[13];
    const float* bd  = (const float*)d_in[14];
    float* out = (float*)d_out;

    cudaFuncSetAttribute(k_qkv_mma,    cudaFuncAttributeMaxDynamicSharedMemorySize, (int)SMEM_BYTES);
    cudaFuncSetAttribute(k_pool_mma,   cudaFuncAttributeMaxDynamicSharedMemorySize, (int)SMEM_BYTES);
    cudaFuncSetAttribute(k_logits_mma, cudaFuncAttributeMaxDynamicSharedMemorySize, (int)SMEM_BYTES);
    cudaFuncSetAttribute(k_av_mma,     cudaFuncAttributeMaxDynamicSharedMemorySize, (int)SMEM_BYTES);
    cudaFuncSetAttribute(k_out_mma,    cudaFuncAttributeMaxDynamicSharedMemorySize, (int)SMEM_BYTES);

    // symbol addresses
    __nv_bfloat16 *xh, *xl, *wh, *wl, *wph, *wpl, *wdh, *wdl;
    __nv_bfloat16 *qkvh, *qkvl, *ph, *pl, *pvth, *pvtl, *ah, *al, *sh, *sl;
    cudaGetSymbolAddress((void**)&xh,   g_xh);
    cudaGetSymbolAddress((void**)&xl,   g_xl);
    cudaGetSymbolAddress((void**)&wh,   g_Wh);
    cudaGetSymbolAddress((void**)&wl,   g_Wl);
    cudaGetSymbolAddress((void**)&wph,  g_Wph);
    cudaGetSymbolAddress((void**)&wpl,  g_Wpl);
    cudaGetSymbolAddress((void**)&wdh,  g_Wdh);
    cudaGetSymbolAddress((void**)&wdl,  g_Wdl);
    cudaGetSymbolAddress((void**)&qkvh, g_QKVh);
    cudaGetSymbolAddress((void**)&qkvl, g_QKVl);
    cudaGetSymbolAddress((void**)&ph,   g_Ph);
    cudaGetSymbolAddress((void**)&pl,   g_Pl);
    cudaGetSymbolAddress((void**)&pvth, g_PVth);
    cudaGetSymbolAddress((void**)&pvtl, g_PVtl);
    cudaGetSymbolAddress((void**)&ah,   g_ah);
    cudaGetSymbolAddress((void**)&al,   g_al);
    cudaGetSymbolAddress((void**)&sh,   g_sh);
    cudaGetSymbolAddress((void**)&sl,   g_sl);

    EncodeFn enc = nullptr;
    {
        void* p = nullptr;
        cudaDriverEntryPointQueryResult st;
        cudaGetDriverEntryPointByVersion("cuTensorMapEncodeTiled", &p, 12000,
                                         cudaEnableDefault, &st);
        enc = (EncodeFn)p;
    }

    const size_t PHSZ = (size_t)BH * LR * HD;     // g_Ph[0] length
    CUtensorMap qAh, qAl, qBh, qBl;               // qkv
    CUtensorMap pAh, pAl, pBh, pBl;               // pool
    CUtensorMap lAh, lAl, lBh, lBl;               // logits
    CUtensorMap vAh, vAl, vBh, vBl;               // av
    CUtensorMap oAh, oAl, oBh, oBl;               // out
    mk2d(enc, &qAh, xh, IND, MP);        mk2d(enc, &qAl, xl, IND, MP);
    mk2d(enc, &qBh, wh, IND, 3 * QKVD);  mk2d(enc, &qBl, wl, IND, 3 * QKVD);
    mk2d(enc, &pAh, qkvh, HD, (uint64_t)3 * BH * L); mk2d(enc, &pAl, qkvl, HD, (uint64_t)3 * BH * L);
    mk2d(enc, &pBh, wph, HD, 3 * HD);    mk2d(enc, &pBl, wpl, HD, 3 * HD);
    mk2d(enc, &lAh, ph, HD, (uint64_t)BH * LR);          mk2d(enc, &lAl, pl, HD, (uint64_t)BH * LR);
    mk2d(enc, &lBh, ph + PHSZ, HD, (uint64_t)BH * LR);   mk2d(enc, &lBl, pl + PHSZ, HD, (uint64_t)BH * LR);
    mk2d(enc, &vAh, ah, KA, (uint64_t)BH * LR);  mk2d(enc, &vAl, al, KA, (uint64_t)BH * LR);
    mk2d(enc, &vBh, pvth, LR, (uint64_t)BH * HD); mk2d(enc, &vBl, pvtl, LR, (uint64_t)BH * HD);
    mk2d(enc, &oAh, sh, QKVD, MP);       mk2d(enc, &oAl, sl, QKVD, MP);
    mk2d(enc, &oBh, wdh, QKVD, IND);     mk2d(enc, &oBl, wdl, QKVD, IND);

    const int nW = QKVD * IND, nP = HD * HD, nX = MQ * IND, nD = IND * QKVD;
    ConvArgs ca;
    ca.seg[0] = { x,   xh,  xl,  nX / 4 };
    ca.seg[1] = { Wq,  wh,                    wl,                    nW / 4 };
    ca.seg[2] = { Wk,  wh + (size_t)nW,       wl + (size_t)nW,       nW / 4 };
    ca.seg[3] = { Wv,  wh + (size_t)2 * nW,   wl + (size_t)2 * nW,   nW / 4 };
    ca.seg[4] = { Wpq, wph,                   wpl,                   nP / 4 };
    ca.seg[5] = { Wpk, wph + (size_t)nP,      wpl + (size_t)nP,      nP / 4 };
    ca.seg[6] = { Wpv, wph + (size_t)2 * nP,  wpl + (size_t)2 * nP,  nP / 4 };
    ca.seg[7] = { Wd,  wdh,                   wdl,                   nD / 4 };
    int maxn4 = nX / 4;                        // x is the largest segment
    k_conv_all<<<dim3((maxn4 + 255) / 256, 8), 256>>>(ca);
    k_pos<<<(1024 * HD + 255) / 256, 256>>>();

    dim3 t(256);
    k_qkv_mma<<<dim3(QKVD / 128, MP / 128, 3), t, SMEM_BYTES>>>(bq, bk, bv, qAh, qAl, qBh, qBl);
    k_cls2<<<(3 * BH * HD + 255) / 256, 256>>>();
    k_pool_mma<<<dim3(HD / 128, BH * 8, 3), t, SMEM_BYTES>>>(bpq, bpk, bpv, pAh, pAl, pBh, pBl);
    k_pvt<<<dim3(LR / 64, HD / 64, BH), 256>>>();
    k_logits_mma<<<dim3(LR / 128, LR / 128, BH), t, SMEM_BYTES>>>(lAh, lAl, lBh, lBl);
    k_softmax_mma<<<dim3(L, BH), 256>>>();
    k_av_mma<<<dim3(HD / 128, LR / 128, BH), t, SMEM_BYTES>>>(vAh, vAl, vBh, vBl);
    k_out_mma<<<dim3(IND / 128, MP / 128), t, SMEM_BYTES>>>(bd, out, oAh, oAl, oBh, oBl);
}

// round 17
// speedup vs baseline: 1.6114x; 1.6114x over previous
#include <cuda.h>
#include <cuda_runtime.h>
#include <cuda_bf16.h>
#include <cstdint>
#include <math.h>

// ============================================================================
// Problem constants
// ============================================================================
static constexpr int Bsz  = 4;
static constexpr int NH   = 8;
static constexpr int L    = 1025;
static constexpr int HD   = 512;
static constexpr int IND  = 512;
static constexpr int QKVD = 4096;
static constexpr int BH   = Bsz * NH;          // 32
static constexpr int MQ   = Bsz * L;           // 4100
static constexpr int MP   = 4224;              // padded M rows (33*128)
static constexpr int LR   = 1152;              // padded rows per (b,n) (9*128)
static constexpr int KA   = 1088;              // padded attn K cols (17*64)
static constexpr int LP   = 1028;              // fp32 logits row stride

// ============================================================================
// Global scratch (zero-initialized; pad regions never written)
// ============================================================================
__device__ __align__(16) __nv_bfloat16 g_xh[MP * IND];
__device__ __align__(16) __nv_bfloat16 g_xl[MP * IND];
__device__ __align__(16) __nv_bfloat16 g_Wh[3][QKVD * IND];
__device__ __align__(16) __nv_bfloat16 g_Wl[3][QKVD * IND];
__device__ __align__(16) __nv_bfloat16 g_Wph[3][HD * HD];
__device__ __align__(16) __nv_bfloat16 g_Wpl[3][HD * HD];
__device__ __align__(16) __nv_bfloat16 g_Wdh[IND * QKVD];
__device__ __align__(16) __nv_bfloat16 g_Wdl[IND * QKVD];
__device__ __align__(16) __nv_bfloat16 g_QKVh[3][(size_t)BH * L * HD];
__device__ __align__(16) __nv_bfloat16 g_QKVl[3][(size_t)BH * L * HD];
__device__ __align__(16) __nv_bfloat16 g_Ph[2][(size_t)BH * LR * HD];    // PQ, PK (token-major)
__device__ __align__(16) __nv_bfloat16 g_Pl[2][(size_t)BH * LR * HD];
__device__ __align__(16) __nv_bfloat16 g_PVth[(size_t)BH * HD * LR];     // PV transposed [hd][token]
__device__ __align__(16) __nv_bfloat16 g_PVtl[(size_t)BH * HD * LR];
__device__ __align__(16) float         g_logits[(size_t)BH * L * LP];
__device__ __align__(16) __nv_bfloat16 g_ah[(size_t)BH * LR * KA];
__device__ __align__(16) __nv_bfloat16 g_al[(size_t)BH * LR * KA];
__device__ __align__(16) __nv_bfloat16 g_sh[(size_t)MP * QKVD];
__device__ __align__(16) __nv_bfloat16 g_sl[(size_t)MP * QKVD];
__device__ __align__(16) float         g_emb[1024 * HD];                 // 2D pos-embed table

// ============================================================================
// GEMM core: 128x128 CTA tile, 8 warps of 64x32, KC=32 k-chunks.
// TMA 2D loads into SW64-swizzled 128x64B tiles, 3-stage mbarrier pipeline.
// Stage t+2 issued at loop TOP (slot aliases t-1, drained by prior syncthreads)
// so two loads stay in flight during every compute phase.
// ============================================================================
#define KC 32
static constexpr uint32_t TILE_B = 128 * KC * 2;      // 8192 bytes per tile
static constexpr uint32_t STG_B  = 4 * TILE_B;        // 32768 per stage
static constexpr uint32_t NSTG   = 3;
static constexpr uint32_t MB_OFF = NSTG * STG_B;      // 98304
static constexpr size_t   SMEM_BYTES = NSTG * STG_B + 64 + 1024;

__device__ __forceinline__ uint32_t smem_u32(const void* p) {
    uint32_t a;
    asm("{ .reg .u64 t; cvta.to.shared.u64 t, %1; cvt.u32.u64 %0, t; }" : "=r"(a) : "l"(p));
    return a;
}

__device__ __forceinline__ void mma_bf16(float* d,
    const uint32_t* a, uint32_t b0, uint32_t b1)
{
    asm volatile(
        "mma.sync.aligned.m16n8k16.row.col.f32.bf16.bf16.f32 "
        "{%0,%1,%2,%3}, {%4,%5,%6,%7}, {%8,%9}, {%0,%1,%2,%3};"
        : "+f"(d[0]), "+f"(d[1]), "+f"(d[2]), "+f"(d[3])
        : "r"(a[0]), "r"(a[1]), "r"(a[2]), "r"(a[3]), "r"(b0), "r"(b1));
}

__device__ __forceinline__ void ldsm4(uint32_t* r, uint32_t addr) {
    asm volatile("ldmatrix.sync.aligned.m8n8.x4.shared.b16 {%0,%1,%2,%3}, [%4];"
        : "=r"(r[0]), "=r"(r[1]), "=r"(r[2]), "=r"(r[3]) : "r"(addr));
}

#define MBARRIER_INIT(mb, cnt) \
    asm volatile("mbarrier.init.shared.b64 [%0], %1;" :: "r"((uint32_t)(mb)), "r"((uint32_t)(cnt)) : "memory")
#define MBARRIER_EXPECT_TX(mb, tx) \
    asm volatile("mbarrier.arrive.expect_tx.shared.b64 _, [%0], %1;" :: "r"((uint32_t)(mb)), "r"((uint32_t)(tx)) : "memory")

#define MBARRIER_WAIT_PARITY(mbar_smem_addr, phase_parity) do { \
    uint32_t _mbar = (uint32_t)(mbar_smem_addr); \
    uint32_t _parity = (uint32_t)(phase_parity); \
    uint32_t _done; \
    asm volatile( \
        "{\n\t.reg .pred p;\n\t" \
        "mbarrier.try_wait.parity.acquire.cta.shared::cta.b64 p, [%1], %2;\n\t" \
        "selp.b32 %0, 1, 0, p;\n\t}" \
        : "=r"(_done) : "r"(_mbar), "r"(_parity) : "memory"); \
    if (!_done) { \
        asm volatile( \
            "{\n\t.reg .pred P1;\n\t" \
            "WAIT_LOOP_%=:\n\t" \
            "mbarrier.try_wait.parity.acquire.cta.shared::cta.b64 P1, [%0], %1, 0x989680;\n\t" \
            "@P1 bra.uni WAIT_DONE_%=;\n\t" \
            "bra.uni WAIT_LOOP_%=;\n\t" \
            "WAIT_DONE_%=:\n\t}" \
            :: "r"(_mbar), "r"(_parity) : "memory"); \
    } \
} while(0)

#define TMA_LOAD_2D(dst, map, cx, cy, mb) \
    asm volatile("cp.async.bulk.tensor.2d.shared::cta.global.tile.mbarrier::complete_tx::bytes " \
        "[%0], [%1, {%2, %3}], [%4];" \
        :: "r"((uint32_t)(dst)), "l"(map), "r"((int)(cx)), "r"((int)(cy)), "r"((uint32_t)(mb)) : "memory")

// SW64 swizzle on logical byte offset within a 128x64B tile
__device__ __forceinline__ uint32_t sw64(uint32_t off) { return off ^ ((off >> 3) & 0x30); }

__device__ __forceinline__ void tma_issue(uint32_t stg0, uint32_t mb0, int u,
    const CUtensorMap* mAh, const CUtensorMap* mAl,
    const CUtensorMap* mBh, const CUtensorMap* mBl, int yA, int yB)
{
    uint32_t su = (uint32_t)(u % NSTG);
    uint32_t dst = stg0 + su * STG_B;
    uint32_t mb  = mb0 + su * 8;
    int cx = u * KC;
    MBARRIER_EXPECT_TX(mb, STG_B);
    TMA_LOAD_2D(dst + 0 * TILE_B, mAh, cx, yA, mb);
    TMA_LOAD_2D(dst + 1 * TILE_B, mAl, cx, yA, mb);
    TMA_LOAD_2D(dst + 2 * TILE_B, mBh, cx, yB, mb);
    TMA_LOAD_2D(dst + 3 * TILE_B, mBl, cx, yB, mb);
}

__device__ __forceinline__ void gemm_tma(uint32_t sbase,
    const CUtensorMap* mAh, const CUtensorMap* mAl,
    const CUtensorMap* mBh, const CUtensorMap* mBl,
    int yA, int yB, int kt, float acc[4][4][4])
{
    const int tid = threadIdx.x, lane = tid & 31, wid = tid >> 5;
    const int wm = wid >> 2, wn = wid & 3;
    const int lrow = (lane & 7) + ((lane >> 3) & 1) * 8;
    const int lcolb = (lane >> 4) * 16;      // byte offset within row

    const uint32_t stg0 = sbase, mb0 = sbase + MB_OFF;

    if (tid == 0) {
        for (uint32_t s = 0; s < NSTG; s++) MBARRIER_INIT(mb0 + s * 8, 1);
    }
    __syncthreads();
    if (tid == 0) {
        tma_issue(stg0, mb0, 0, mAh, mAl, mBh, mBl, yA, yB);
        if (kt > 1) tma_issue(stg0, mb0, 1, mAh, mAl, mBh, mBl, yA, yB);
    }

    int ph0 = 0, ph1 = 0, ph2 = 0;
    for (int t = 0; t < kt; t++) {
        const int s = t % NSTG;
        if (s == 0)      { MBARRIER_WAIT_PARITY(mb0 + 0, ph0); ph0 ^= 1; }
        else if (s == 1) { MBARRIER_WAIT_PARITY(mb0 + 8, ph1); ph1 ^= 1; }
        else             { MBARRIER_WAIT_PARITY(mb0 + 16, ph2); ph2 ^= 1; }

        // Deep prefetch: slot (t+2)%3 aliases slot t-1, fully drained by the
        // __syncthreads at the end of iteration t-1 -> safe to re-arm now.
        if (tid == 0 && t + 2 < kt)
            tma_issue(stg0, mb0, t + 2, mAh, mAl, mBh, mBl, yA, yB);

        const uint32_t so = stg0 + (uint32_t)s * STG_B;
        const uint32_t tAh = so, tAl = so + TILE_B, tBh = so + 2 * TILE_B, tBl = so + 3 * TILE_B;
#pragma unroll
        for (int kk = 0; kk < 2; kk++) {
            const int kb = kk * 32 + lcolb;          // byte offset in 64B row
            uint32_t bh[2][4], bl[2][4];
#pragma unroll
            for (int jj = 0; jj < 2; jj++) {
                uint32_t off = sw64((uint32_t)((wn * 32 + jj * 16 + lrow) * 64 + kb));
                ldsm4(bh[jj], tBh + off);
                ldsm4(bl[jj], tBl + off);
            }
#pragma unroll
            for (int i = 0; i < 4; i++) {
                uint32_t ah[4], al[4];
                uint32_t off = sw64((uint32_t)((wm * 64 + i * 16 + lrow) * 64 + kb));
                ldsm4(ah, tAh + off);
                ldsm4(al, tAl + off);
#pragma unroll
                for (int j = 0; j < 4; j++) {
                    uint32_t b0 = bh[j >> 1][j & 1], b1 = bh[j >> 1][2 + (j & 1)];
                    uint32_t c0 = bl[j >> 1][j & 1], c1 = bl[j >> 1][2 + (j & 1)];
                    mma_bf16(acc[i][j], ah, b0, b1);
                    mma_bf16(acc[i][j], ah, c0, c1);
                    mma_bf16(acc[i][j], al, b0, b1);
                }
            }
        }
        __syncthreads();                              // all warps done with stage s
    }
}

__device__ __forceinline__ void split_bf(float v, __nv_bfloat16* hp, __nv_bfloat16* lp) {
    __nv_bfloat16 h = __float2bfloat16(v);
    *hp = h;
    *lp = __float2bfloat16(v - __bfloat162float(h));
}

#define EPI_SETUP() \
    const int lane = threadIdx.x & 31, wid_ = threadIdx.x >> 5; \
    const int wm = wid_ >> 2, wn = wid_ & 3; \
    const int er0 = wm * 64 + (lane >> 2); \
    const int ec0 = wn * 32 + (lane & 3) * 2;

#define SMEM_PROLOG() \
    extern __shared__ char smem_raw[]; \
    uint32_t sbase = (smem_u32(smem_raw) + 1023u) & ~1023u;

// ============================================================================
// Pos-embed table
// ============================================================================
__global__ __launch_bounds__(256) void k_pos()
{
    int idx = blockIdx.x * 256 + threadIdx.x;
    if (idx >= 1024 * HD) return;
    int s = idx >> 9, o = idx & 511;
    const float LOG1E4_128 = 9.210340371976184f / 128.0f;
    int yg = s >> 5, xg = s & 31;
    float omega = expf(-(float)(o & 127) * LOG1E4_128);
    float e;
    if (o < 128)      e = sinf((float)yg * omega);
    else if (o < 256) e = cosf((float)yg * omega);
    else if (o < 384) e = sinf((float)xg * omega);
    else              e = cosf((float)xg * omega);
    g_emb[idx] = e;
}

// ============================================================================
// Fused conversion: fp32 -> bf16 hi/lo, 8 segments
// ============================================================================
struct ConvSeg { const float* s; __nv_bfloat16* h; __nv_bfloat16* l; int n4; };
struct ConvArgs { ConvSeg seg[8]; };

__global__ __launch_bounds__(256) void k_conv_all(ConvArgs a)
{
    ConvSeg sg = a.seg[blockIdx.y];
    int i = blockIdx.x * 256 + threadIdx.x;
    if (i >= sg.n4) return;
    float4 v = ((const float4*)sg.s)[i];
    __nv_bfloat16 h0, h1, h2, h3, l0, l1, l2, l3;
    split_bf(v.x, &h0, &l0); split_bf(v.y, &h1, &l1);
    split_bf(v.z, &h2, &l2); split_bf(v.w, &h3, &l3);
    ushort4 hv = make_ushort4(*(unsigned short*)&h0, *(unsigned short*)&h1,
                              *(unsigned short*)&h2, *(unsigned short*)&h3);
    ushort4 lv = make_ushort4(*(unsigned short*)&l0, *(unsigned short*)&l1,
                              *(unsigned short*)&l2, *(unsigned short*)&l3);
    *(ushort4*)(sg.h + (size_t)i * 4) = hv;
    *(ushort4*)(sg.l + (size_t)i * 4) = lv;
}

// ============================================================================
// QKV projection.  grid (32, 33, 3)
// ============================================================================
__global__ __launch_bounds__(256, 2) void k_qkv_mma(
    const float* __restrict__ bq, const float* __restrict__ bk, const float* __restrict__ bv,
    const __grid_constant__ CUtensorMap mAh, const __grid_constant__ CUtensorMap mAl,
    const __grid_constant__ CUtensorMap mBh, const __grid_constant__ CUtensorMap mBl)
{
    SMEM_PROLOG();
    const int z = blockIdx.z;
    const int row0 = blockIdx.y * 128, col0 = blockIdx.x * 128;
    const float* bias = (z == 0) ? bq : (z == 1) ? bk : bv;

    float acc[4][4][4] = {};
    gemm_tma(sbase, &mAh, &mAl, &mBh, &mBl, row0, z * QKVD + col0, IND / KC, acc);

    EPI_SETUP();
    __nv_bfloat16* oh = g_QKVh[z];
    __nv_bfloat16* ol = g_QKVl[z];
#pragma unroll
    for (int i = 0; i < 4; i++)
#pragma unroll
        for (int p2 = 0; p2 < 2; p2++) {
            int m = row0 + er0 + i * 16 + p2 * 8;
            if (m >= MQ) continue;
            int bb = m / L, l = m - bb * L;
#pragma unroll
            for (int j = 0; j < 4; j++)
#pragma unroll
                for (int p1 = 0; p1 < 2; p1++) {
                    int o = col0 + ec0 + j * 8 + p1;
                    int n = o >> 9, ch = o & 511;
                    float v = acc[i][j][p2 * 2 + p1] + bias[o];
                    size_t idx = (((size_t)(bb * NH + n)) * L + l) * HD + ch;
                    split_bf(v, &oh[idx], &ol[idx]);
                }
        }
}

// ============================================================================
// cls passthrough
// ============================================================================
__global__ __launch_bounds__(256) void k_cls2()
{
    int idx = blockIdx.x * 256 + threadIdx.x;
    if (idx >= 3 * BH * HD) return;
    int z = idx / (BH * HD), rem = idx % (BH * HD);
    int bn = rem / HD, c = rem % HD;
    size_t so = ((size_t)bn * L) * HD + c;
    if (z < 2) {
        size_t d = ((size_t)bn * LR) * HD + c;
        g_Ph[z][d] = g_QKVh[z][so];
        g_Pl[z][d] = g_QKVl[z][so];
    } else {
        size_t d = ((size_t)bn * HD + c) * LR;   // token 0
        g_PVth[d] = g_QKVh[2][so];
        g_PVtl[d] = g_QKVl[2][so];
    }
}

// ============================================================================
// Pooler GEMM.  grid (4, 256, 3); y = bn*8 + mt.  z==2 writes PV transposed
// (scattered stores measured cheaper than an extra gmem round-trip: R16).
// ============================================================================
__global__ __launch_bounds__(256, 2) void k_pool_mma(
    const float* __restrict__ bpq, const float* __restrict__ bpk, const float* __restrict__ bpv,
    const __grid_constant__ CUtensorMap mAh, const __grid_constant__ CUtensorMap mAl,
    const __grid_constant__ CUtensorMap mBh, const __grid_constant__ CUtensorMap mBl)
{
    SMEM_PROLOG();
    const int z = blockIdx.z;
    const int bn = blockIdx.y >> 3, mt = blockIdx.y & 7;
    const int col0 = blockIdx.x * 128;
    const float* bias = (z == 0) ? bpq : (z == 1) ? bpk : bpv;

    int yA = z * (BH * L) + bn * L + 1 + mt * 128;
    int yB = z * HD + col0;
    float acc[4][4][4] = {};
    gemm_tma(sbase, &mAh, &mAl, &mBh, &mBl, yA, yB, HD / KC, acc);

    EPI_SETUP();
#pragma unroll
    for (int i = 0; i < 4; i++)
#pragma unroll
        for (int p2 = 0; p2 < 2; p2++) {
            int s = mt * 128 + er0 + i * 16 + p2 * 8;     // spatial token 0..1023
#pragma unroll
            for (int j = 0; j < 4; j++)
#pragma unroll
                for (int p1 = 0; p1 < 2; p1++) {
                    int o = col0 + ec0 + j * 8 + p1;
                    float v = acc[i][j][p2 * 2 + p1] + bias[o];
                    if (z == 0) v += g_emb[(size_t)s * HD + o];
                    if (z < 2) {
                        size_t idx = ((size_t)bn * LR + 1 + s) * HD + o;
                        split_bf(v, &g_Ph[z][idx], &g_Pl[z][idx]);
                    } else {
                        size_t idx = ((size_t)bn * HD + o) * LR + 1 + s;
                        split_bf(v, &g_PVth[idx], &g_PVtl[idx]);
                    }
                }
        }
}

// ============================================================================
// Logits = PQ * PK^T * scale.  grid (9, 9, 32)
// ============================================================================
__global__ __launch_bounds__(256, 2) void k_logits_mma(
    const __grid_constant__ CUtensorMap mAh, const __grid_constant__ CUtensorMap mAl,
    const __grid_constant__ CUtensorMap mBh, const __grid_constant__ CUtensorMap mBl)
{
    SMEM_PROLOG();
    const int bn = blockIdx.z;
    const int row0 = blockIdx.y * 128, col0 = blockIdx.x * 128;

    float acc[4][4][4] = {};
    gemm_tma(sbase, &mAh, &mAl, &mBh, &mBl, bn * LR + row0, bn * LR + col0, HD / KC, acc);

    EPI_SETUP();
    const float scale = 0.044194173824159216f;   // 1/sqrt(512)
    float* dstb = g_logits + (size_t)bn * L * LP;
#pragma unroll
    for (int i = 0; i < 4; i++)
#pragma unroll
        for (int p2 = 0; p2 < 2; p2++) {
            int q = row0 + er0 + i * 16 + p2 * 8;
            if (q >= L) continue;
            float* dst = dstb + (size_t)q * LP;
#pragma unroll
            for (int j = 0; j < 4; j++)
#pragma unroll
                for (int p1 = 0; p1 < 2; p1++) {
                    int k = col0 + ec0 + j * 8 + p1;
                    if (k < L) dst[k] = acc[i][j][p2 * 2 + p1] * scale;
                }
        }
}

// ============================================================================
// Softmax -> attn hi/lo bf16.  grid (1025, 32)
// ============================================================================
__global__ __launch_bounds__(256) void k_softmax_mma()
{
    const int bn = blockIdx.y, row = blockIdx.x;
    const float* p = g_logits + ((size_t)bn * L + row) * LP;
    __nv_bfloat16* oh = g_ah + ((size_t)bn * LR + row) * KA;
    __nv_bfloat16* ol = g_al + ((size_t)bn * LR + row) * KA;
    __shared__ float red[256];
    const int tid = threadIdx.x;

    float v[5];
#pragma unroll
    for (int i = 0; i < 4; i++) v[i] = p[tid + (i << 8)];
    v[4] = (tid == 0) ? p[1024] : -1e30f;

    float m = v[0];
#pragma unroll
    for (int i = 1; i < 5; i++) m = fmaxf(m, v[i]);
    red[tid] = m; __syncthreads();
    for (int s = 128; s > 0; s >>= 1) {
        if (tid < s) red[tid] = fmaxf(red[tid], red[tid + s]);
        __syncthreads();
    }
    m = red[0]; __syncthreads();

    float sum = 0.f;
#pragma unroll
    for (int i = 0; i < 5; i++) { v[i] = expf(v[i] - m); sum += v[i]; }
    red[tid] = sum; __syncthreads();
    for (int s = 128; s > 0; s >>= 1) {
        if (tid < s) red[tid] += red[tid + s];
        __syncthreads();
    }
    float inv = 1.f / red[0];

#pragma unroll
    for (int i = 0; i < 4; i++) {
        int k = tid + (i << 8);
        split_bf(v[i] * inv, &oh[k], &ol[k]);
    }
    if (tid == 0) split_bf(v[4] * inv, &oh[1024], &ol[1024]);
}

// ============================================================================
// AV GEMM + residual + restack.  grid (4, 9, 32)
// ============================================================================
__global__ __launch_bounds__(256, 2) void k_av_mma(
    const __grid_constant__ CUtensorMap mAh, const __grid_constant__ CUtensorMap mAl,
    const __grid_constant__ CUtensorMap mBh, const __grid_constant__ CUtensorMap mBl)
{
    SMEM_PROLOG();
    const int bn = blockIdx.z;
    const int row0 = blockIdx.y * 128, col0 = blockIdx.x * 128;

    float acc[4][4][4] = {};
    gemm_tma(sbase, &mAh, &mAl, &mBh, &mBl, bn * LR + row0, bn * HD + col0, KA / KC, acc);

    EPI_SETUP();
    const int bb = bn >> 3, n = bn & 7;
#pragma unroll
    for (int i = 0; i < 4; i++)
#pragma unroll
        for (int p2 = 0; p2 < 2; p2++) {
            int l = row0 + er0 + i * 16 + p2 * 8;
            if (l >= L) continue;
            size_t qb = ((size_t)bn * L + l) * HD;
            size_t sb = ((size_t)(bb * L + l)) * QKVD + n * HD;
#pragma unroll
            for (int j = 0; j < 4; j++)
#pragma unroll
                for (int p1 = 0; p1 < 2; p1++) {
                    int c = col0 + ec0 + j * 8 + p1;
                    float v = acc[i][j][p2 * 2 + p1];
                    if (l > 0)
                        v += __bfloat162float(g_QKVh[0][qb + c]) + __bfloat162float(g_QKVl[0][qb + c]);
                    split_bf(v, &g_sh[sb + c], &g_sl[sb + c]);
                }
        }
}

// ============================================================================
// Output projection.  grid (4, 33)
// ============================================================================
__global__ __launch_bounds__(256, 2) void k_out_mma(
    const float* __restrict__ bd, float* __restrict__ out,
    const __grid_constant__ CUtensorMap mAh, const __grid_constant__ CUtensorMap mAl,
    const __grid_constant__ CUtensorMap mBh, const __grid_constant__ CUtensorMap mBl)
{
    SMEM_PROLOG();
    const int row0 = blockIdx.y * 128, col0 = blockIdx.x * 128;

    float acc[4][4][4] = {};
    gemm_tma(sbase, &mAh, &mAl, &mBh, &mBl, row0, col0, QKVD / KC, acc);

    EPI_SETUP();
#pragma unroll
    for (int i = 0; i < 4; i++)
#pragma unroll
        for (int p2 = 0; p2 < 2; p2++) {
            int m = row0 + er0 + i * 16 + p2 * 8;
            if (m >= MQ) continue;
            float* dst = out + (size_t)m * IND;
#pragma unroll
            for (int j = 0; j < 4; j++)
#pragma unroll
                for (int p1 = 0; p1 < 2; p1++) {
                    int o = col0 + ec0 + j * 8 + p1;
                    dst[o] = acc[i][j][p2 * 2 + p1] + bd[o];
                }
        }
}

// ============================================================================
// Host: tensormap encoding via driver entry point (no -lcuda needed)
// ============================================================================
typedef CUresult (*EncodeFn)(CUtensorMap*, CUtensorMapDataType, cuuint32_t, void*,
    const cuuint64_t*, const cuuint64_t*, const cuuint32_t*, const cuuint32_t*,
    CUtensorMapInterleave, CUtensorMapSwizzle, CUtensorMapL2promotion, CUtensorMapFloatOOBfill);

static void mk2d(EncodeFn enc, CUtensorMap* m, void* base, uint64_t d0, uint64_t d1)
{
    cuuint64_t dims[2] = {d0, d1};
    cuuint64_t strides[1] = {d0 * 2};          // bf16
    cuuint32_t box[2] = {KC, 128};
    cuuint32_t es[2] = {1, 1};
    enc(m, CU_TENSOR_MAP_DATA_TYPE_UINT16, 2, base, dims, strides, box, es,
        CU_TENSOR_MAP_INTERLEAVE_NONE, CU_TENSOR_MAP_SWIZZLE_64B,
        CU_TENSOR_MAP_L2_PROMOTION_L2_128B, CU_TENSOR_MAP_FLOAT_OOB_FILL_NONE);
}

extern "C" void kernel_launch(void* const* d_in, const int* in_sizes, int n_in,
                              void* d_out, int out_size)
{
    const float* x   = (const float*)d_in[0];
    const float* Wq  = (const float*)d_in[1];
    const float* bq  = (const float*)d_in[2];
    const float* Wk  = (const float*)d_in[3];
    const float* bk  = (const float*)d_in[4];
    const float* Wv  = (const float*)d_in[5];
    const float* bv  = (const float*)d_in[6];
    const float* Wpq = (const float*)d_in[7];
    const float* bpq = (const float*)d_in[8];
    const float* Wpk = (const float*)d_in[9];
    const float* bpk = (const float*)d_in[10];
    const float* Wpv = (const float*)d_in[11];
    const float* bpv = (const float*)d_in[12];
    const float* Wd  = (const float*)d_in[13];
    const float* bd  = (const float*)d_in[14];
    float* out = (float*)d_out;

    cudaFuncSetAttribute(k_qkv_mma,    cudaFuncAttributeMaxDynamicSharedMemorySize, (int)SMEM_BYTES);
    cudaFuncSetAttribute(k_pool_mma,   cudaFuncAttributeMaxDynamicSharedMemorySize, (int)SMEM_BYTES);
    cudaFuncSetAttribute(k_logits_mma, cudaFuncAttributeMaxDynamicSharedMemorySize, (int)SMEM_BYTES);
    cudaFuncSetAttribute(k_av_mma,     cudaFuncAttributeMaxDynamicSharedMemorySize, (int)SMEM_BYTES);
    cudaFuncSetAttribute(k_out_mma,    cudaFuncAttributeMaxDynamicSharedMemorySize, (int)SMEM_BYTES);

    // symbol addresses
    __nv_bfloat16 *xh, *xl, *wh, *wl, *wph, *wpl, *wdh, *wdl;
    __nv_bfloat16 *qkvh, *qkvl, *ph, *pl, *pvth, *pvtl, *ah, *al, *sh, *sl;
    cudaGetSymbolAddress((void**)&xh,   g_xh);
    cudaGetSymbolAddress((void**)&xl,   g_xl);
    cudaGetSymbolAddress((void**)&wh,   g_Wh);
    cudaGetSymbolAddress((void**)&wl,   g_Wl);
    cudaGetSymbolAddress((void**)&wph,  g_Wph);
    cudaGetSymbolAddress((void**)&wpl,  g_Wpl);
    cudaGetSymbolAddress((void**)&wdh,  g_Wdh);
    cudaGetSymbolAddress((void**)&wdl,  g_Wdl);
    cudaGetSymbolAddress((void**)&qkvh, g_QKVh);
    cudaGetSymbolAddress((void**)&qkvl, g_QKVl);
    cudaGetSymbolAddress((void**)&ph,   g_Ph);
    cudaGetSymbolAddress((void**)&pl,   g_Pl);
    cudaGetSymbolAddress((void**)&pvth, g_PVth);
    cudaGetSymbolAddress((void**)&pvtl, g_PVtl);
    cudaGetSymbolAddress((void**)&ah,   g_ah);
    cudaGetSymbolAddress((void**)&al,   g_al);
    cudaGetSymbolAddress((void**)&sh,   g_sh);
    cudaGetSymbolAddress((void**)&sl,   g_sl);

    EncodeFn enc = nullptr;
    {
        void* p = nullptr;
        cudaDriverEntryPointQueryResult st;
        cudaGetDriverEntryPointByVersion("cuTensorMapEncodeTiled", &p, 12000,
                                         cudaEnableDefault, &st);
        enc = (EncodeFn)p;
    }

    const size_t PHSZ = (size_t)BH * LR * HD;     // g_Ph[0] length
    CUtensorMap qAh, qAl, qBh, qBl;               // qkv
    CUtensorMap pAh, pAl, pBh, pBl;               // pool
    CUtensorMap lAh, lAl, lBh, lBl;               // logits
    CUtensorMap vAh, vAl, vBh, vBl;               // av
    CUtensorMap oAh, oAl, oBh, oBl;               // out
    mk2d(enc, &qAh, xh, IND, MP);        mk2d(enc, &qAl, xl, IND, MP);
    mk2d(enc, &qBh, wh, IND, 3 * QKVD);  mk2d(enc, &qBl, wl, IND, 3 * QKVD);
    mk2d(enc, &pAh, qkvh, HD, (uint64_t)3 * BH * L); mk2d(enc, &pAl, qkvl, HD, (uint64_t)3 * BH * L);
    mk2d(enc, &pBh, wph, HD, 3 * HD);    mk2d(enc, &pBl, wpl, HD, 3 * HD);
    mk2d(enc, &lAh, ph, HD, (uint64_t)BH * LR);          mk2d(enc, &lAl, pl, HD, (uint64_t)BH * LR);
    mk2d(enc, &lBh, ph + PHSZ, HD, (uint64_t)BH * LR);   mk2d(enc, &lBl, pl + PHSZ, HD, (uint64_t)BH * LR);
    mk2d(enc, &vAh, ah, KA, (uint64_t)BH * LR);  mk2d(enc, &vAl, al, KA, (uint64_t)BH * LR);
    mk2d(enc, &vBh, pvth, LR, (uint64_t)BH * HD); mk2d(enc, &vBl, pvtl, LR, (uint64_t)BH * HD);
    mk2d(enc, &oAh, sh, QKVD, MP);       mk2d(enc, &oAl, sl, QKVD, MP);
    mk2d(enc, &oBh, wdh, QKVD, IND);     mk2d(enc, &oBl, wdl, QKVD, IND);

    const int nW = QKVD * IND, nP = HD * HD, nX = MQ * IND, nD = IND * QKVD;
    ConvArgs ca;
    ca.seg[0] = { x,   xh,  xl,  nX / 4 };
    ca.seg[1] = { Wq,  wh,                    wl,                    nW / 4 };
    ca.seg[2] = { Wk,  wh + (size_t)nW,       wl + (size_t)nW,       nW / 4 };
    ca.seg[3] = { Wv,  wh + (size_t)2 * nW,   wl + (size_t)2 * nW,   nW / 4 };
    ca.seg[4] = { Wpq, wph,                   wpl,                   nP / 4 };
    ca.seg[5] = { Wpk, wph + (size_t)nP,      wpl + (size_t)nP,      nP / 4 };
    ca.seg[6] = { Wpv, wph + (size_t)2 * nP,  wpl + (size_t)2 * nP,  nP / 4 };
    ca.seg[7] = { Wd,  wdh,                   wdl,                   nD / 4 };
    int maxn4 = nX / 4;                        // x is the largest segment
    k_conv_all<<<dim3((maxn4 + 255) / 256, 8), 256>>>(ca);
    k_pos<<<(1024 * HD + 255) / 256, 256>>>();

    dim3 t(256);
    k_qkv_mma<<<dim3(QKVD / 128, MP / 128, 3), t, SMEM_BYTES>>>(bq, bk, bv, qAh, qAl, qBh, qBl);
    k_cls2<<<(3 * BH * HD + 255) / 256, 256>>>();
    k_pool_mma<<<dim3(HD / 128, BH * 8, 3), t, SMEM_BYTES>>>(bpq, bpk, bpv, pAh, pAl, pBh, pBl);
    k_logits_mma<<<dim3(LR / 128, LR / 128, BH), t, SMEM_BYTES>>>(lAh, lAl, lBh, lBl);
    k_softmax_mma<<<dim3(L, BH), 256>>>();
    k_av_mma<<<dim3(HD / 128, LR / 128, BH), t, SMEM_BYTES>>>(vAh, vAl, vBh, vBl);
    k_out_mma<<<dim3(IND / 128, MP / 128), t, SMEM_BYTES>>>(bd, out, oAh, oAl, oBh, oBl);
}